// round 3
// baseline (speedup 1.0000x reference)
#include <cuda_runtime.h>
#include <math.h>
#include <stdint.h>

#define MAX_N 2048
#define MAX_E 32768
#define RFANf   0.14433756729740643f  // 1/sqrt(48)
#define RSQRT3f 0.57735026918962576f
#define RS32f   0.17677669529663687f  // 1/sqrt(32)

__device__ float d_q0g[MAX_N*32];
__device__ float d_q1g[MAX_N*48];
__device__ float d_v0e[(size_t)MAX_E*32];
__device__ float d_v1e[(size_t)MAX_E*48];
__device__ float d_logits[MAX_E*4];
__device__ float d_exb[MAX_E*4];
__device__ float d_segmax[MAX_N*4];
__device__ float d_denom[MAX_N*4];
__device__ float d_agg0[MAX_N*32];
__device__ float d_agg1[MAX_N*48];

__device__ __forceinline__ void atomicMaxF(float* a, float v){
  if (v >= 0.f) atomicMax((int*)a, __float_as_int(v));
  else atomicMin((unsigned int*)a, __float_as_uint(v));
}

__global__ void k_init(int N){
  int t = blockIdx.x*blockDim.x+threadIdx.x;
  if (t < N*4){ d_segmax[t] = -10.0f; d_denom[t] = 0.0f; }
  if (t < N*32) d_agg0[t] = 0.0f;
  if (t < N*48) d_agg1[t] = 0.0f;
}

__global__ void k_q(const float* __restrict__ nf, const float* __restrict__ Wq0,
                    const float* __restrict__ Wq1, int N){
  int t = blockIdx.x*blockDim.x+threadIdx.x;
  if (t >= N*80) return;
  int n = t/80, r = t - n*80;
  if (r < 32){
    int h = r>>3, w = r&7;
    const float* s = nf + (size_t)n*80;
    float acc = 0.f;
#pragma unroll
    for (int u = 0; u < 32; u++) acc += s[u]*Wq0[h*256+u*8+w];
    d_q0g[n*32+r] = acc*RS32f;
  } else {
    int rr = r-32, h = rr/12, q = rr - h*12, w = q/3, i = q - w*3;
    const float* v = nf + (size_t)n*80 + 32;
    float acc = 0.f;
#pragma unroll
    for (int u = 0; u < 16; u++) acc += v[u*3+i]*Wq1[h*64+u*4+w];
    d_q1g[n*48+rr] = acc*0.25f;
  }
}

// ---- smem layout (floats) ----
#define OFF_HT  0
#define OFF_W2  8192
#define OFF_WT  16384
#define OFF_O0  20736
#define OFF_S1  24832
#define OFF_V1  26880
#define OFF_SS  33024
#define OFF_VV  35072
#define OFF_CVV 38144
#define OFF_SH  39168
#define OFF_EMB 39424
#define OFF_WD  40448
#define OFF_IDX 40576
#define SMEM_FLOATS 40704
#define SMEM_BYTES (SMEM_FLOATS*4)

__device__ __forceinline__ void cp16(float* dst, const float* src){
  uint32_t a = (uint32_t)__cvta_generic_to_shared(dst);
  asm volatile("cp.async.cg.shared.global [%0], [%1], 16;" :: "r"(a), "l"(src));
}

__global__ void __launch_bounds__(256,1) k_edge(
    const float* __restrict__ nf, const int* __restrict__ ei,
    const float* __restrict__ esh, const float* __restrict__ emb,
    const float* __restrict__ W1k, const float* __restrict__ b1k,
    const float* __restrict__ W2k, const float* __restrict__ b2k,
    const float* __restrict__ W1v, const float* __restrict__ b1v,
    const float* __restrict__ W2v, const float* __restrict__ b2v,
    const float* __restrict__ Wd0, const float* __restrict__ Wd1,
    int N, int E)
{
  extern __shared__ float sm[];
  float* sHT  = sm + OFF_HT;
  float* sW2  = sm + OFF_W2;
  float* sWT  = sm + OFF_WT;
  float* sO0  = sm + OFF_O0;
  float* sS1  = sm + OFF_S1;
  float* sV1  = sm + OFF_V1;
  float* sSS  = sm + OFF_SS;
  float* sVV  = sm + OFF_VV;
  float* sCVV = sm + OFF_CVV;
  float* sSH  = sm + OFF_SH;
  float* sEmb = sm + OFF_EMB;
  float* sWD  = sm + OFF_WD;
  int*   sIdx = (int*)(sm + OFF_IDX);

  const int t = threadIdx.x;
  const int eg0 = blockIdx.x*64;
  const int tx = t & 15, ty = t >> 4;

  // prefetch first W2 tile (set k, j0=0) into buffer 0
  {
    int col = tx<<2;
#pragma unroll
    for (int c = 0; c < 4; c++){
      int r = ty + 16*c;
      cp16(sW2 + r*64 + col, W2k + (size_t)r*2304 + col);
    }
    asm volatile("cp.async.commit_group;");
  }

  if (t < 128){
    int e = t & 63, which = t >> 6;
    int eg = eg0 + e;
    sIdx[t] = (eg < E) ? ei[(size_t)which*E + eg] : 0;
  }
  {
    int e = t >> 2, c = t & 3;
    int eg = eg0 + e;
    bool val = eg < E;
    sSH[e*4+c] = val ? esh[(size_t)eg*4+c] : 0.f;
    float4 z = make_float4(0,0,0,0);
    float4 d = val ? *(const float4*)(emb + (size_t)eg*16 + c*4) : z;
    *(float4*)(sEmb + e*16 + c*4) = d;
  }
  for (int i = t; i < 1024; i += 256){ sWT[i] = W1k[i]; sWT[1024+i] = W1v[i]; }
  if (t < 64){ sWT[2048+t] = b1k[t]; sWT[2112+t] = b1v[t]; }
  if (t < 64) sWD[t] = Wd0[t];
  else if (t < 80) sWD[t] = Wd1[t-64];
  for (int i = t; i < 12288; i += 256) sO0[i] = 0.f;  // zeroes O0,S1,V1
  __syncthreads();

  // gather src node features
  {
    int e = t >> 2, part = t & 3;
    const float4* row = (const float4*)(nf + (size_t)sIdx[e]*80);
#pragma unroll
    for (int q = 0; q < 5; q++){
      int f4 = part*5 + q;
      float4 d = row[f4];
      if (f4 < 8) *((float4*)(sSS + e*32) + f4) = d;
      else        *((float4*)(sVV + e*48) + (f4-8)) = d;
    }
  }
  __syncthreads();

  // cvv and hE (both sets)
  for (int i = t; i < 1024; i += 256){
    int e = i >> 4, u = i & 15;
    const float* vv = sVV + e*48 + u*3;
    sCVV[i] = (vv[0]*sSH[e*4+1] + vv[1]*sSH[e*4+2] + vv[2]*sSH[e*4+3]) * RSQRT3f;
  }
  {
    int e = t >> 2, kq = (t & 3) << 4;
#pragma unroll
    for (int s = 0; s < 2; s++){
      const float* W1s = sWT + s*1024;
      const float* b1s = sWT + 2048 + s*64;
      for (int kk = 0; kk < 16; kk++){
        int k = kq + kk;
        float acc = b1s[k];
#pragma unroll
        for (int b = 0; b < 16; b++) acc += sEmb[e*16+b]*W1s[b*64+k];
        sHT[s*4096 + k*64 + e] = acc/(1.f+expf(-acc));
      }
    }
  }
  __syncthreads();

  for (int it = 0; it < 72; it++){
    int buf = it & 1;
    int s = (it >= 36) ? 1 : 0;
    int j0 = (it - s*36) << 6;

    if (it + 1 < 72){
      int s2 = ((it+1) >= 36) ? 1 : 0;
      int j02 = ((it+1) - s2*36) << 6;
      const float* W2n = s2 ? W2v : W2k;
      float* db = sW2 + (buf^1)*4096;
      int col = tx<<2;
#pragma unroll
      for (int c = 0; c < 4; c++){
        int r = ty + 16*c;
        cp16(db + r*64 + col, W2n + (size_t)r*2304 + j02 + col);
      }
      asm volatile("cp.async.commit_group;");
      asm volatile("cp.async.wait_group 1;");
    } else {
      asm volatile("cp.async.wait_group 0;");
    }
    __syncthreads();   // W2[buf] ready; previous epilogue done with sWT

    float a00=0,a01=0,a02=0,a03=0,a10=0,a11=0,a12=0,a13=0;
    float a20=0,a21=0,a22=0,a23=0,a30=0,a31=0,a32=0,a33=0;
    const float* aB = sHT + s*4096 + (ty<<2);
    const float* bB = sW2 + buf*4096 + (tx<<2);
#pragma unroll 8
    for (int k = 0; k < 64; k++){
      float4 av = *(const float4*)(aB + (k<<6));
      float4 bv = *(const float4*)(bB + (k<<6));
      a00+=av.x*bv.x; a01+=av.x*bv.y; a02+=av.x*bv.z; a03+=av.x*bv.w;
      a10+=av.y*bv.x; a11+=av.y*bv.y; a12+=av.y*bv.z; a13+=av.y*bv.w;
      a20+=av.z*bv.x; a21+=av.z*bv.y; a22+=av.z*bv.z; a23+=av.z*bv.w;
      a30+=av.w*bv.x; a31+=av.w*bv.y; a32+=av.w*bv.z; a33+=av.w*bv.w;
    }
    const float* b2p = s ? b2v : b2k;
    float4 bias = *(const float4*)(b2p + j0 + (tx<<2));
    {
      float* wp = sWT + (ty*4)*68 + (tx<<2);
      *(float4*)(wp)      = make_float4(a00+bias.x,a01+bias.y,a02+bias.z,a03+bias.w);
      *(float4*)(wp+68)   = make_float4(a10+bias.x,a11+bias.y,a12+bias.z,a13+bias.w);
      *(float4*)(wp+136)  = make_float4(a20+bias.x,a21+bias.y,a22+bias.z,a23+bias.w);
      *(float4*)(wp+204)  = make_float4(a30+bias.x,a31+bias.y,a32+bias.z,a33+bias.w);
    }
    __syncthreads();

    int h = j0/576, off0 = j0 - h*576;
    if (off0 < 256){                       // ss -> out0 (coeff ss[u]*sh0)
      int u0 = off0 >> 3;
      for (int p = t; p < 512; p += 256){
        int e = p >> 3, ow = p & 7;
        float acc = 0.f;
#pragma unroll
        for (int du = 0; du < 8; du++) acc += sSS[e*32+u0+du]*sWT[e*68+du*8+ow];
        sO0[s*2048 + e*32 + h*8 + ow] += acc*sSH[e*4];
      }
    } else if (off0 < 384){                // vv -> out0 (coeff cvv[u])
      int u0 = (off0-256) >> 3;
      for (int p = t; p < 512; p += 256){
        int e = p >> 3, ow = p & 7;
        float acc = 0.f;
#pragma unroll
        for (int du = 0; du < 8; du++) acc += sCVV[e*16+u0+du]*sWT[e*68+du*8+ow];
        sO0[s*2048 + e*32 + h*8 + ow] += acc;
      }
    } else if (off0 < 512){                // sv -> s1 (coeff ss[u])
      int u0 = (off0-384) >> 2;
      int e = t >> 2, w1 = t & 3;
      float acc = 0.f;
#pragma unroll
      for (int du = 0; du < 16; du++) acc += sSS[e*32+u0+du]*sWT[e*68+du*4+w1];
      sS1[s*1024 + e*16 + h*4 + w1] += acc;
    } else {                               // vs -> v1 (coeff vv[u,i]*sh0)
      for (int p = t; p < 768; p += 256){
        int e = p/12, r = p - e*12, w1 = r/3, i = r - w1*3;
        float acc = 0.f;
#pragma unroll
        for (int du = 0; du < 16; du++) acc += sVV[e*48+du*3+i]*sWT[e*68+du*4+w1];
        sV1[s*3072 + e*48 + h*12 + w1*3 + i] += acc*sSH[e*4];
      }
    }
  }
  __syncthreads();

  // write v-set outputs
  for (int p = t; p < 2048; p += 256){
    int e = p >> 5, c = p & 31;
    int eg = eg0 + e;
    if (eg < E) d_v0e[(size_t)eg*32 + c] = sO0[2048 + e*32 + c]*RFANf;
  }
  for (int p = t; p < 3072; p += 256){
    int e = p/48, r = p - e*48;
    int h = r/12, q = r - h*12, w1 = q/3, i = q - w1*3;
    int eg = eg0 + e;
    if (eg < E)
      d_v1e[(size_t)eg*48 + r] =
        (sS1[1024 + e*16 + h*4 + w1]*sSH[e*4+1+i] + sV1[3072 + e*48 + r])*RFANf;
  }

  // logits (k-set) : 4 threads per edge
  {
    int e = t >> 2, h = t & 3;
    int eg = eg0 + e;
    int dst = sIdx[64 + e];
    float k0[8];
#pragma unroll
    for (int w = 0; w < 8; w++) k0[w] = sO0[e*32 + h*8 + w]*RFANf;
    const float* q0 = d_q0g + dst*32 + h*8;
    float l0 = 0.f;
#pragma unroll
    for (int v = 0; v < 8; v++){
      float tv = 0.f;
#pragma unroll
      for (int u = 0; u < 8; u++) tv += q0[u]*sWD[u*8+v];
      l0 += tv*k0[v];
    }
    float k1[12];
#pragma unroll
    for (int w1 = 0; w1 < 4; w1++)
#pragma unroll
      for (int i = 0; i < 3; i++)
        k1[w1*3+i] = (sS1[e*16+h*4+w1]*sSH[e*4+1+i] + sV1[e*48+h*12+w1*3+i])*RFANf;
    const float* q1 = d_q1g + dst*48 + h*12;
    float l1 = 0.f;
#pragma unroll
    for (int u = 0; u < 4; u++)
#pragma unroll
      for (int v = 0; v < 4; v++){
        float d3 = q1[u*3]*k1[v*3] + q1[u*3+1]*k1[v*3+1] + q1[u*3+2]*k1[v*3+2];
        l1 += sWD[64 + u*4 + v]*d3;
      }
    float lg = (l0 + l1*RSQRT3f)*0.025f;   // /sqrt(80)/sqrt(20)
    lg = fminf(fmaxf(lg, -10.f), 10.f);
    if (eg < E){
      d_logits[eg*4 + h] = lg;
      atomicMaxF(d_segmax + dst*4 + h, lg);
    }
  }
}

__global__ void k_ex(const int* __restrict__ ei, int E){
  int t = blockIdx.x*blockDim.x+threadIdx.x;
  if (t >= E*4) return;
  int e = t >> 2, h = t & 3;
  int dst = ei[E + e];
  float ex = expf(d_logits[t] - d_segmax[dst*4+h]);
  d_exb[t] = ex;
  atomicAdd(d_denom + dst*4 + h, ex);
}

__global__ void k_agg(const int* __restrict__ ei, int E){
  int t = blockIdx.x*blockDim.x+threadIdx.x;
  if (t >= E*80) return;
  int e = t/80, r = t - e*80;
  int dst = ei[E + e];
  if (r < 32){
    int h = r >> 3;
    float alpha = d_exb[e*4+h]/(d_denom[dst*4+h] + 1e-12f);
    atomicAdd(d_agg0 + dst*32 + r, alpha*d_v0e[(size_t)e*32 + r]);
  } else {
    int r2 = r - 32, h = r2/12;
    float alpha = d_exb[e*4+h]/(d_denom[dst*4+h] + 1e-12f);
    atomicAdd(d_agg1 + dst*48 + r2, alpha*d_v1e[(size_t)e*48 + r2]);
  }
}

__global__ void k_node(const float* __restrict__ nf,
    const float* __restrict__ Wo0, const float* __restrict__ Wo1,
    const float* __restrict__ Wf10, const float* __restrict__ Wf11,
    const float* __restrict__ Wf20, const float* __restrict__ Wf21,
    float* __restrict__ out, int N)
{
  __shared__ float sx0[32], sx1[48], sa0[64], sa1[48];
  int n = blockIdx.x, t = threadIdx.x;
  if (t < 32){
    float acc = 0.f;
#pragma unroll
    for (int u = 0; u < 32; u++) acc += d_agg0[n*32+u]*Wo0[u*32+t];
    sx0[t] = nf[(size_t)n*80 + t] + acc*RS32f;
  } else if (t < 80){
    int r = t-32, w = r/3, i = r - w*3;
    float acc = 0.f;
#pragma unroll
    for (int u = 0; u < 16; u++) acc += d_agg1[n*48+u*3+i]*Wo1[u*16+w];
    sx1[r] = nf[(size_t)n*80 + 32 + r] + acc*0.25f;
  }
  __syncthreads();
  if (t < 64){
    float acc = 0.f;
#pragma unroll
    for (int u = 0; u < 32; u++) acc += sx0[u]*Wf10[u*64+t];
    float a = acc*RS32f;
    sa0[t] = a/(1.f+expf(-a));
  } else if (t < 112){
    int r = t-64, w = r/3, i = r - w*3;
    float acc = 0.f;
#pragma unroll
    for (int u = 0; u < 16; u++) acc += sx1[u*3+i]*Wf11[u*16+w];
    sa1[r] = acc*0.25f;
  }
  __syncthreads();
  if (t < 16){
    float x = sa1[t*3], y = sa1[t*3+1], z = sa1[t*3+2];
    float nm = sqrtf(x*x+y*y+z*z);
    float g = (nm < 1e-8f) ? 0.f : (nm/(1.f+expf(-nm)))/nm;
    sa1[t*3] = x*g; sa1[t*3+1] = y*g; sa1[t*3+2] = z*g;
  }
  __syncthreads();
  if (t < 32){
    float acc = 0.f;
#pragma unroll
    for (int u = 0; u < 64; u++) acc += sa0[u]*Wf20[u*32+t];
    out[(size_t)n*80 + t] = sx0[t] + acc*0.125f;
  } else if (t < 80){
    int r = t-32, w = r/3, i = r - w*3;
    float acc = 0.f;
#pragma unroll
    for (int u = 0; u < 16; u++) acc += sa1[u*3+i]*Wf21[u*16+w];
    out[(size_t)n*80 + t] = sx1[r] + acc*0.25f;
  }
}

extern "C" void kernel_launch(void* const* d_in, const int* in_sizes, int n_in,
                              void* d_out, int out_size){
  const float* nf   = (const float*)d_in[0];
  const int*   ei   = (const int*)  d_in[1];
  const float* esh  = (const float*)d_in[2];
  const float* emb  = (const float*)d_in[3];
  const float* Wq0  = (const float*)d_in[4];
  const float* Wq1  = (const float*)d_in[5];
  const float* Wk1  = (const float*)d_in[6];
  const float* bk1  = (const float*)d_in[7];
  const float* Wk2  = (const float*)d_in[8];
  const float* bk2  = (const float*)d_in[9];
  const float* Wv1  = (const float*)d_in[10];
  const float* bv1  = (const float*)d_in[11];
  const float* Wv2  = (const float*)d_in[12];
  const float* bv2  = (const float*)d_in[13];
  const float* Wd0  = (const float*)d_in[14];
  const float* Wd1  = (const float*)d_in[15];
  const float* Wo0  = (const float*)d_in[16];
  const float* Wo1  = (const float*)d_in[17];
  const float* Wf10 = (const float*)d_in[18];
  const float* Wf11 = (const float*)d_in[19];
  const float* Wf20 = (const float*)d_in[20];
  const float* Wf21 = (const float*)d_in[21];
  float* out = (float*)d_out;

  int N = in_sizes[0]/80;
  int E = in_sizes[1]/2;

  static int smem_set = 0;
  if (!smem_set){
    cudaFuncSetAttribute(k_edge, cudaFuncAttributeMaxDynamicSharedMemorySize, SMEM_BYTES);
    smem_set = 1;
  }

  k_init<<<(N*48+255)/256, 256>>>(N);
  k_q<<<(N*80+255)/256, 256>>>(nf, Wq0, Wq1, N);
  k_edge<<<(E+63)/64, 256, SMEM_BYTES>>>(nf, ei, esh, emb,
      Wk1, bk1, Wk2, bk2, Wv1, bv1, Wv2, bv2, Wd0, Wd1, N, E);
  k_ex<<<(E*4+255)/256, 256>>>(ei, E);
  k_agg<<<(E*80+255)/256, 256>>>(ei, E);
  k_node<<<N, 128>>>(nf, Wo0, Wo1, Wf10, Wf11, Wf20, Wf21, out, N);
}